// round 1
// baseline (speedup 1.0000x reference)
#include <cuda_runtime.h>
#include <math.h>

#define NN 50000
#define EE 800000
#define TE (EE + NN)   // edges + self loops = 850000

// ---------------- scratch buffers (static device allocation) ----------------
__device__ __align__(16) float g_h1  [NN * 256];
__device__ __align__(16) float g_agg1[NN * 256];
__device__ __align__(16) float g_x1  [NN * 256];
__device__ __align__(16) float g_h2  [NN * 64];
__device__ __align__(16) float g_agg2[NN * 64];
__device__ __align__(16) float g_x2  [NN * 64];
__device__ __align__(16) float g_h3  [NN * 64];
__device__ __align__(16) float g_agg3[NN * 64];
__device__ __align__(16) float g_x3  [NN * 64];
__device__ __align__(16) float g_p1  [NN * 128];
__device__ float g_es1  [NN * 4];
__device__ float g_ed1  [NN * 4];
__device__ float g_emax1[NN * 4];
__device__ float g_den1 [NN * 4];
__device__ float g_es2  [NN];
__device__ float g_ed2  [NN];
__device__ float g_emax2[NN];
__device__ float g_den2 [NN];
__device__ float g_deg  [NN];
__device__ float g_s1[512];   // sum[256], sumsq[256]
__device__ float g_s2[128];
__device__ float g_s3[128];

enum {
    B_H1, B_AGG1, B_X1, B_H2, B_AGG2, B_X2, B_H3, B_AGG3, B_X3, B_P1,
    B_ES1, B_ED1, B_EMAX1, B_DEN1, B_ES2, B_ED2, B_EMAX2, B_DEN2, B_DEG,
    B_S1, B_S2, B_S3
};

__device__ __forceinline__ float* buf(int s) {
    switch (s) {
        case B_H1:    return g_h1;
        case B_AGG1:  return g_agg1;
        case B_X1:    return g_x1;
        case B_H2:    return g_h2;
        case B_AGG2:  return g_agg2;
        case B_X2:    return g_x2;
        case B_H3:    return g_h3;
        case B_AGG3:  return g_agg3;
        case B_X3:    return g_x3;
        case B_P1:    return g_p1;
        case B_ES1:   return g_es1;
        case B_ED1:   return g_ed1;
        case B_EMAX1: return g_emax1;
        case B_DEN1:  return g_den1;
        case B_ES2:   return g_es2;
        case B_ED2:   return g_ed2;
        case B_EMAX2: return g_emax2;
        case B_DEN2:  return g_den2;
        case B_DEG:   return g_deg;
        case B_S1:    return g_s1;
        case B_S2:    return g_s2;
        case B_S3:    return g_s3;
    }
    return nullptr;
}

// ---------------- helpers ----------------
__device__ __forceinline__ void atomicMaxF(float* addr, float v) {
    // monotonic int/uint mapping trick; valid across sign mixes and -inf init
    if (v >= 0.f) atomicMax((int*)addr, __float_as_int(v));
    else          atomicMin((unsigned int*)addr, __float_as_uint(v));
}

__device__ __forceinline__ void redAdd4(float* p, float a, float b, float c, float d) {
    asm volatile("red.global.add.v4.f32 [%0], {%1, %2, %3, %4};"
                 :: "l"(p), "f"(a), "f"(b), "f"(c), "f"(d) : "memory");
}

__device__ __forceinline__ float lrelu(float v) { return v > 0.f ? v : 0.2f * v; }

// ---------------- generic kernels ----------------
__global__ void fill_k(int sel, float v, int n) {
    float* p = buf(sel);
    for (int i = blockIdx.x * blockDim.x + threadIdx.x; i < n; i += gridDim.x * blockDim.x)
        p[i] = v;
}

// C[n,M] = A[n,K] @ B[K,M] (+bias)(+relu).  BM=BN=64, BK=16, 256 thr, 4x4 microtile.
__global__ void gemm_k(int aSel, const float* __restrict__ aRaw,
                       const float* __restrict__ B, const float* __restrict__ bias,
                       int cSel, float* cRaw,
                       int n, int K, int M, int act) {
    const float* A = (aSel >= 0) ? buf(aSel) : aRaw;
    float*       C = (cSel >= 0) ? buf(cSel) : cRaw;
    __shared__ float As[16][64];
    __shared__ float Bs[16][64];
    int bm = blockIdx.y * 64, bn = blockIdx.x * 64;
    int tid = threadIdx.x;
    int tx = tid & 15, ty = tid >> 4;
    float acc[4][4];
#pragma unroll
    for (int i = 0; i < 4; i++)
#pragma unroll
        for (int j = 0; j < 4; j++) acc[i][j] = 0.f;

    for (int k0 = 0; k0 < K; k0 += 16) {
#pragma unroll 4
        for (int i = tid; i < 1024; i += 256) {
            int r = i >> 4, c = i & 15;
            int row = bm + r;
            As[c][r] = (row < n) ? A[row * K + k0 + c] : 0.f;
        }
#pragma unroll 4
        for (int i = tid; i < 1024; i += 256) {
            int r = i >> 6, c = i & 63;
            Bs[r][c] = B[(k0 + r) * M + bn + c];
        }
        __syncthreads();
#pragma unroll
        for (int kk = 0; kk < 16; kk++) {
            float a[4], bb[4];
#pragma unroll
            for (int i = 0; i < 4; i++) a[i] = As[kk][ty * 4 + i];
#pragma unroll
            for (int j = 0; j < 4; j++) bb[j] = Bs[kk][tx * 4 + j];
#pragma unroll
            for (int i = 0; i < 4; i++)
#pragma unroll
                for (int j = 0; j < 4; j++) acc[i][j] += a[i] * bb[j];
        }
        __syncthreads();
    }
#pragma unroll
    for (int i = 0; i < 4; i++) {
        int row = bm + ty * 4 + i;
        if (row >= n) continue;
#pragma unroll
        for (int j = 0; j < 4; j++) {
            int col = bn + tx * 4 + j;
            float v = acc[i][j];
            if (act >= 1) v += bias[col];
            if (act == 2) v = fmaxf(v, 0.f);
            C[row * M + col] = v;
        }
    }
}

// per-node attention dots: es[n,h] = sum_d h[n,h,d]*asrc[h,d]; same for ed.
// blockDim = H*64 (256 for H=4, 64 for H=1)
__global__ void attn_dots_k(int hSel, const float* __restrict__ asrc, const float* __restrict__ adst,
                            int esSel, int edSel, int H) {
    const float* Hm = buf(hSel);
    int node = blockIdx.x;
    int t = threadIdx.x;
    float v = Hm[node * (H * 64) + t];
    float s = v * asrc[t];
    float d = v * adst[t];
#pragma unroll
    for (int off = 16; off > 0; off >>= 1) {
        s += __shfl_down_sync(0xffffffff, s, off);
        d += __shfl_down_sync(0xffffffff, d, off);
    }
    __shared__ float sh[8][2];
    int w = t >> 5;
    if ((t & 31) == 0) { sh[w][0] = s; sh[w][1] = d; }
    __syncthreads();
    if (t < H) {
        buf(esSel)[node * H + t] = sh[2 * t][0] + sh[2 * t + 1][0];
        buf(edSel)[node * H + t] = sh[2 * t][1] + sh[2 * t + 1][1];
    }
}

__global__ void edge_max_k(const int* __restrict__ ei, int esSel, int edSel, int emSel, int H) {
    int i = blockIdx.x * blockDim.x + threadIdx.x;
    if (i >= TE * H) return;
    int e = i / H, h = i - e * H;
    int s, t;
    if (e < EE) { s = ei[e]; t = ei[EE + e]; } else { s = t = e - EE; }
    float v = lrelu(buf(esSel)[s * H + h] + buf(edSel)[t * H + h]);
    atomicMaxF(&buf(emSel)[t * H + h], v);
}

// GAT layer 1 (H=4): one warp per (edge, head-pair); 16 lanes per head, v4 reductions.
__global__ void gat_scatter4_k(const int* __restrict__ ei) {
    int wt = (blockIdx.x * blockDim.x + threadIdx.x) >> 5;
    int lane = threadIdx.x & 31;
    if (wt >= TE * 2) return;
    int e = wt >> 1;
    int hd = ((wt & 1) << 1) + (lane >> 4);
    int s, t;
    if (e < EE) { s = ei[e]; t = ei[EE + e]; } else { s = t = e - EE; }
    float v = lrelu(g_es1[s * 4 + hd] + g_ed1[t * 4 + hd]);
    float w = __expf(v - g_emax1[t * 4 + hd]);
    if ((lane & 15) == 0) atomicAdd(&g_den1[t * 4 + hd], w);
    int d = (lane & 15) << 2;
    const float4 hv = *reinterpret_cast<const float4*>(&g_h1[s * 256 + hd * 64 + d]);
    redAdd4(&g_agg1[t * 256 + hd * 64 + d], w * hv.x, w * hv.y, w * hv.z, w * hv.w);
}

// GAT layer 2 (H=1): one warp per 2 edges; 16 lanes per edge.
__global__ void gat_scatter1_k(const int* __restrict__ ei) {
    int wt = (blockIdx.x * blockDim.x + threadIdx.x) >> 5;
    int lane = threadIdx.x & 31;
    int e = wt * 2 + (lane >> 4);
    if (e >= TE) return;
    int s, t;
    if (e < EE) { s = ei[e]; t = ei[EE + e]; } else { s = t = e - EE; }
    float v = lrelu(g_es2[s] + g_ed2[t]);
    float w = __expf(v - g_emax2[t]);
    if ((lane & 15) == 0) atomicAdd(&g_den2[t], w);
    int d = (lane & 15) << 2;
    const float4 hv = *reinterpret_cast<const float4*>(&g_h3[s * 64 + d]);
    redAdd4(&g_agg3[t * 64 + d], w * hv.x, w * hv.y, w * hv.z, w * hv.w);
}

__global__ void deg_k(const int* __restrict__ ei) {
    int i = blockIdx.x * blockDim.x + threadIdx.x;
    if (i >= TE) return;
    int t = (i < EE) ? ei[EE + i] : (i - EE);
    atomicAdd(&g_deg[t], 1.f);
}

// GCN scatter: one warp per 2 edges.
__global__ void gcn_scatter_k(const int* __restrict__ ei) {
    int wt = (blockIdx.x * blockDim.x + threadIdx.x) >> 5;
    int lane = threadIdx.x & 31;
    int e = wt * 2 + (lane >> 4);
    if (e >= TE) return;
    int s, t;
    if (e < EE) { s = ei[e]; t = ei[EE + e]; } else { s = t = e - EE; }
    float nrm = rsqrtf(g_deg[s]) * rsqrtf(g_deg[t]);   // deg >= 1 (self loops)
    int d = (lane & 15) << 2;
    const float4 hv = *reinterpret_cast<const float4*>(&g_h2[s * 64 + d]);
    redAdd4(&g_agg2[t * 64 + d], nrm * hv.x, nrm * hv.y, nrm * hv.z, nrm * hv.w);
}

// normalize by softmax denom + bias
__global__ void finalize_gat_k(int aggSel, int denSel, const float* __restrict__ bias, int H) {
    float* agg = buf(aggSel);
    const float* den = buf(denSel);
    int total = NN * H * 64;
    int HD = H * 64;
    for (int i = blockIdx.x * blockDim.x + threadIdx.x; i < total; i += gridDim.x * blockDim.x) {
        int fd = i % HD;
        int nI = i / HD;
        int h = fd >> 6;
        agg[i] = agg[i] / (den[nI * H + h] + 1e-16f) + bias[fd];
    }
}

__global__ void add_bias_k(int sel, const float* __restrict__ bias, int F) {
    float* x = buf(sel);
    int total = NN * F;
    for (int i = blockIdx.x * blockDim.x + threadIdx.x; i < total; i += gridDim.x * blockDim.x)
        x[i] += bias[i % F];
}

// per-feature sum & sumsq (coalesced: thread -> feature)
__global__ void bn_stats_k(int xSel, int sSel, int F) {
    const float* x = buf(xSel);
    float* sums = buf(sSel);
    int t = threadIdx.x;            // 256 threads
    int f = t % F;
    int rpb = 256 / F;
    int r = blockIdx.x * rpb + t / F;
    int stride = gridDim.x * rpb;
    float s = 0.f, sq = 0.f;
    for (; r < NN; r += stride) {
        float v = x[r * F + f];
        s += v; sq += v * v;
    }
    atomicAdd(&sums[f], s);
    atomicAdd(&sums[F + f], sq);
}

// y = act( (x - mu) * rsqrt(var+eps) * g + beta ),  act: 1=ELU, 2=ReLU
__global__ void bn_apply_k(int xSel, int ySel, int sSel,
                           const float* __restrict__ g, const float* __restrict__ beta,
                           int F, int act) {
    const float* x = buf(xSel);
    float* y = buf(ySel);
    const float* sums = buf(sSel);
    const float invN = 1.f / (float)NN;
    int total = NN * F;
    for (int i = blockIdx.x * blockDim.x + threadIdx.x; i < total; i += gridDim.x * blockDim.x) {
        int f = i % F;
        float mu = sums[f] * invN;
        float var = fmaxf(sums[F + f] * invN - mu * mu, 0.f);
        float v = (x[i] - mu) * rsqrtf(var + 1e-5f) * g[f] + beta[f];
        y[i] = (act == 1) ? (v > 0.f ? v : expm1f(v)) : fmaxf(v, 0.f);
    }
}

// ---------------- host ----------------
static inline int cdiv(int a, int b) { return (a + b - 1) / b; }

extern "C" void kernel_launch(void* const* d_in, const int* in_sizes, int n_in,
                              void* d_out, int out_size) {
    const float* x   = (const float*)d_in[0];
    const int*   ei  = (const int*)  d_in[1];
    // d_in[2] = edge_attr (ignored by the model)
    const float* W1  = (const float*)d_in[3];
    const float* as1 = (const float*)d_in[4];
    const float* ad1 = (const float*)d_in[5];
    const float* b1  = (const float*)d_in[6];
    const float* g1  = (const float*)d_in[7];
    const float* be1 = (const float*)d_in[8];
    const float* Wg  = (const float*)d_in[9];
    const float* bg  = (const float*)d_in[10];
    const float* g2  = (const float*)d_in[11];
    const float* be2 = (const float*)d_in[12];
    const float* W2  = (const float*)d_in[13];
    const float* as2 = (const float*)d_in[14];
    const float* ad2 = (const float*)d_in[15];
    const float* b2  = (const float*)d_in[16];
    const float* g3  = (const float*)d_in[17];
    const float* be3 = (const float*)d_in[18];
    const float* Wp1 = (const float*)d_in[19];
    const float* bp1 = (const float*)d_in[20];
    const float* Wp2 = (const float*)d_in[21];
    const float* bp2 = (const float*)d_in[22];
    float* out = (float*)d_out;

    const int TPB = 256;
    // ---- zero / init scratch ----
    fill_k<<<cdiv(NN * 4, TPB), TPB>>>(B_EMAX1, -INFINITY, NN * 4);
    fill_k<<<cdiv(NN * 4, TPB), TPB>>>(B_DEN1, 0.f, NN * 4);
    fill_k<<<cdiv(NN * 256, TPB), TPB>>>(B_AGG1, 0.f, NN * 256);
    fill_k<<<cdiv(NN, TPB), TPB>>>(B_EMAX2, -INFINITY, NN);
    fill_k<<<cdiv(NN, TPB), TPB>>>(B_DEN2, 0.f, NN);
    fill_k<<<cdiv(NN * 64, TPB), TPB>>>(B_AGG2, 0.f, NN * 64);
    fill_k<<<cdiv(NN * 64, TPB), TPB>>>(B_AGG3, 0.f, NN * 64);
    fill_k<<<cdiv(NN, TPB), TPB>>>(B_DEG, 0.f, NN);
    fill_k<<<2, TPB>>>(B_S1, 0.f, 512);
    fill_k<<<1, TPB>>>(B_S2, 0.f, 128);
    fill_k<<<1, TPB>>>(B_S3, 0.f, 128);

    // ---- GAT layer 1 ----
    {   // h1 = x @ W1   [N,128]x[128,256]
        dim3 grid(256 / 64, cdiv(NN, 64));
        gemm_k<<<grid, 256>>>(-1, x, W1, nullptr, B_H1, nullptr, NN, 128, 256, 0);
    }
    attn_dots_k<<<NN, 256>>>(B_H1, as1, ad1, B_ES1, B_ED1, 4);
    edge_max_k<<<cdiv(TE * 4, TPB), TPB>>>(ei, B_ES1, B_ED1, B_EMAX1, 4);
    gat_scatter4_k<<<cdiv(TE * 2 * 32, TPB), TPB>>>(ei);
    finalize_gat_k<<<4096, TPB>>>(B_AGG1, B_DEN1, b1, 4);
    bn_stats_k<<<512, TPB>>>(B_AGG1, B_S1, 256);
    bn_apply_k<<<4096, TPB>>>(B_AGG1, B_X1, B_S1, g1, be1, 256, 1);   // ELU

    // ---- GCN ----
    {   // h2 = x1 @ Wg  [N,256]x[256,64]
        dim3 grid(64 / 64, cdiv(NN, 64));
        gemm_k<<<grid, 256>>>(B_X1, nullptr, Wg, nullptr, B_H2, nullptr, NN, 256, 64, 0);
    }
    deg_k<<<cdiv(TE, TPB), TPB>>>(ei);
    gcn_scatter_k<<<cdiv(cdiv(TE, 2) * 32, TPB), TPB>>>(ei);
    add_bias_k<<<4096, TPB>>>(B_AGG2, bg, 64);
    bn_stats_k<<<512, TPB>>>(B_AGG2, B_S2, 64);
    bn_apply_k<<<4096, TPB>>>(B_AGG2, B_X2, B_S2, g2, be2, 64, 2);    // ReLU

    // ---- GAT layer 2 (H=1, concat=False -> identity over 1 head) ----
    {   // h3 = x2 @ W2  [N,64]x[64,64]
        dim3 grid(64 / 64, cdiv(NN, 64));
        gemm_k<<<grid, 256>>>(B_X2, nullptr, W2, nullptr, B_H3, nullptr, NN, 64, 64, 0);
    }
    attn_dots_k<<<NN, 64>>>(B_H3, as2, ad2, B_ES2, B_ED2, 1);
    edge_max_k<<<cdiv(TE, TPB), TPB>>>(ei, B_ES2, B_ED2, B_EMAX2, 1);
    gat_scatter1_k<<<cdiv(cdiv(TE, 2) * 32, TPB), TPB>>>(ei);
    finalize_gat_k<<<4096, TPB>>>(B_AGG3, B_DEN2, b2, 1);
    bn_stats_k<<<512, TPB>>>(B_AGG3, B_S3, 64);
    bn_apply_k<<<4096, TPB>>>(B_AGG3, B_X3, B_S3, g3, be3, 64, 1);    // ELU

    // ---- projector ----
    {   // p1 = relu(x3 @ Wp1 + bp1)  [N,64]x[64,128]
        dim3 grid(128 / 64, cdiv(NN, 64));
        gemm_k<<<grid, 256>>>(B_X3, nullptr, Wp1, bp1, B_P1, nullptr, NN, 64, 128, 2);
    }
    {   // out = p1 @ Wp2 + bp2       [N,128]x[128,64]
        dim3 grid(64 / 64, cdiv(NN, 64));
        gemm_k<<<grid, 256>>>(B_P1, nullptr, Wp2, bp2, -1, out, NN, 128, 64, 1);
    }
}

// round 4
// speedup vs baseline: 1.2436x; 1.2436x over previous
#include <cuda_runtime.h>
#include <math.h>

#define NN 50000
#define EE 800000
#define TE (EE + NN)   // edges + self loops = 850000

// ---------------- scratch buffers (static device allocation) ----------------
__device__ __align__(16) float g_h1  [NN * 256];
__device__ __align__(16) float g_agg1[NN * 256];
__device__ __align__(16) float g_h2  [NN * 64];
__device__ __align__(16) float g_agg2[NN * 64];
__device__ __align__(16) float g_h3  [NN * 64];
__device__ __align__(16) float g_agg3[NN * 64];
__device__ __align__(16) float g_p1  [NN * 128];
__device__ __align__(16) float g_es1  [NN * 4];
__device__ __align__(16) float g_ed1  [NN * 4];
__device__ __align__(16) float g_den1 [NN * 4];
__device__ __align__(16) float g_es2  [NN];
__device__ __align__(16) float g_ed2  [NN];
__device__ __align__(16) float g_den2 [NN];
__device__ __align__(16) float g_deg  [NN];
__device__ __align__(16) float g_s1[512];   // sum[256], sumsq[256]
__device__ __align__(16) float g_s2[128];
__device__ __align__(16) float g_s3[128];
__device__ __align__(16) float g_sc1[256];
__device__ __align__(16) float g_sh1[256];
__device__ __align__(16) float g_sc2[64];
__device__ __align__(16) float g_sh2[64];
__device__ __align__(16) float g_sc3[64];
__device__ __align__(16) float g_sh3[64];

enum {
    B_H1, B_AGG1, B_H2, B_AGG2, B_H3, B_AGG3, B_P1,
    B_ES1, B_ED1, B_DEN1, B_ES2, B_ED2, B_DEN2, B_DEG,
    B_S1, B_S2, B_S3,
    B_SC1, B_SH1, B_SC2, B_SH2, B_SC3, B_SH3
};

__device__ __forceinline__ float* buf(int s) {
    switch (s) {
        case B_H1:   return g_h1;
        case B_AGG1: return g_agg1;
        case B_H2:   return g_h2;
        case B_AGG2: return g_agg2;
        case B_H3:   return g_h3;
        case B_AGG3: return g_agg3;
        case B_P1:   return g_p1;
        case B_ES1:  return g_es1;
        case B_ED1:  return g_ed1;
        case B_DEN1: return g_den1;
        case B_ES2:  return g_es2;
        case B_ED2:  return g_ed2;
        case B_DEN2: return g_den2;
        case B_DEG:  return g_deg;
        case B_S1:   return g_s1;
        case B_S2:   return g_s2;
        case B_S3:   return g_s3;
        case B_SC1:  return g_sc1;
        case B_SH1:  return g_sh1;
        case B_SC2:  return g_sc2;
        case B_SH2:  return g_sh2;
        case B_SC3:  return g_sc3;
        case B_SH3:  return g_sh3;
    }
    return nullptr;
}

// ---------------- helpers ----------------
__device__ __forceinline__ void redAdd4(float* p, float a, float b, float c, float d) {
    asm volatile("red.global.add.v4.f32 [%0], {%1, %2, %3, %4};"
                 :: "l"(p), "f"(a), "f"(b), "f"(c), "f"(d) : "memory");
}

__device__ __forceinline__ float lrelu(float v) { return v > 0.f ? v : 0.2f * v; }
__device__ __forceinline__ float eluf(float v)  { return v > 0.f ? v : expm1f(v); }

// ---------------- fills ----------------
__global__ void fill_k(int sel, float v, int n) {
    float* p = buf(sel);
    for (int i = blockIdx.x * blockDim.x + threadIdx.x; i < n; i += gridDim.x * blockDim.x)
        p[i] = v;
}

// ---------------- GEMM: C[n,M] = actOut( actIn(A*sc+sh)[n,K] @ B[K,M] + bias ) ----------------
// BM=128, BN=64, BK=16, 256 threads, 8x4 microtile, float4 everywhere.
// scSel/shSel < 0 -> raw A. inAct: 1=ELU, 2=ReLU (applied to transformed A elements).
// bias != null -> add per-col bias. outRelu -> clamp at 0.
__global__ void __launch_bounds__(256) gemm_k(
        int aSel, const float* __restrict__ aRaw, const float* __restrict__ B,
        int cSel, float* cRaw, int n, int K, int M,
        int scSel, int shSel, int inAct,
        const float* __restrict__ bias, int outRelu) {
    const float* A = (aSel >= 0) ? buf(aSel) : aRaw;
    float*       C = (cSel >= 0) ? buf(cSel) : cRaw;
    const float* sc = (scSel >= 0) ? buf(scSel) : nullptr;
    const float* sh = (shSel >= 0) ? buf(shSel) : nullptr;

    __shared__ float As[16][132];
    __shared__ float Bs[16][68];

    const int bm = blockIdx.y * 128, bn = blockIdx.x * 64;
    const int tid = threadIdx.x;
    const int tx = tid & 15, ty = tid >> 4;

    float acc[8][4];
#pragma unroll
    for (int i = 0; i < 8; i++)
#pragma unroll
        for (int j = 0; j < 4; j++) acc[i][j] = 0.f;

    for (int k0 = 0; k0 < K; k0 += 16) {
        // load A tile: 128 rows x 16 k  (512 float4, 2 per thread)
#pragma unroll
        for (int it = 0; it < 2; it++) {
            int j = it * 256 + tid;
            int r = j >> 2, c = (j & 3) * 4;
            int row = bm + r;
            float4 v = make_float4(0.f, 0.f, 0.f, 0.f);
            if (row < n) v = *reinterpret_cast<const float4*>(&A[row * K + k0 + c]);
            if (sc) {
                float4 s4 = *reinterpret_cast<const float4*>(&sc[k0 + c]);
                float4 h4 = *reinterpret_cast<const float4*>(&sh[k0 + c]);
                v.x = v.x * s4.x + h4.x; v.y = v.y * s4.y + h4.y;
                v.z = v.z * s4.z + h4.z; v.w = v.w * s4.w + h4.w;
                if (inAct == 1) { v.x = eluf(v.x); v.y = eluf(v.y); v.z = eluf(v.z); v.w = eluf(v.w); }
                else            { v.x = fmaxf(v.x, 0.f); v.y = fmaxf(v.y, 0.f);
                                  v.z = fmaxf(v.z, 0.f); v.w = fmaxf(v.w, 0.f); }
                if (row >= n) v = make_float4(0.f, 0.f, 0.f, 0.f);
            }
            As[c + 0][r] = v.x; As[c + 1][r] = v.y; As[c + 2][r] = v.z; As[c + 3][r] = v.w;
        }
        // load B tile: 16 rows x 64 cols (256 float4, 1 per thread)
        {
            int r = tid >> 4, c = (tid & 15) * 4;
            float4 v = *reinterpret_cast<const float4*>(&B[(k0 + r) * M + bn + c]);
            *reinterpret_cast<float4*>(&Bs[r][c]) = v;
        }
        __syncthreads();
#pragma unroll
        for (int kk = 0; kk < 16; kk++) {
            float4 a0 = *reinterpret_cast<const float4*>(&As[kk][ty * 8]);
            float4 a1 = *reinterpret_cast<const float4*>(&As[kk][ty * 8 + 4]);
            float4 b  = *reinterpret_cast<const float4*>(&Bs[kk][tx * 4]);
            float a[8] = {a0.x, a0.y, a0.z, a0.w, a1.x, a1.y, a1.z, a1.w};
            float bb[4] = {b.x, b.y, b.z, b.w};
#pragma unroll
            for (int i = 0; i < 8; i++)
#pragma unroll
                for (int j = 0; j < 4; j++) acc[i][j] += a[i] * bb[j];
        }
        __syncthreads();
    }

    float4 bv = make_float4(0.f, 0.f, 0.f, 0.f);
    if (bias) bv = *reinterpret_cast<const float4*>(&bias[bn + tx * 4]);
#pragma unroll
    for (int i = 0; i < 8; i++) {
        int row = bm + ty * 8 + i;
        if (row >= n) continue;
        float4 o = make_float4(acc[i][0] + bv.x, acc[i][1] + bv.y,
                               acc[i][2] + bv.z, acc[i][3] + bv.w);
        if (outRelu) { o.x = fmaxf(o.x, 0.f); o.y = fmaxf(o.y, 0.f);
                       o.z = fmaxf(o.z, 0.f); o.w = fmaxf(o.w, 0.f); }
        *reinterpret_cast<float4*>(&C[row * M + bn + tx * 4]) = o;
    }
}

// ---------------- attention dots ----------------
// es[n,h] = sum_d h[n,h,d]*asrc[h,d]; ed likewise. blockDim = H*64.
__global__ void attn_dots_k(int hSel, const float* __restrict__ asrc, const float* __restrict__ adst,
                            int esSel, int edSel, int H) {
    const float* Hm = buf(hSel);
    int node = blockIdx.x;
    int t = threadIdx.x;
    float v = Hm[node * (H * 64) + t];
    float s = v * asrc[t];
    float d = v * adst[t];
#pragma unroll
    for (int off = 16; off > 0; off >>= 1) {
        s += __shfl_down_sync(0xffffffff, s, off);
        d += __shfl_down_sync(0xffffffff, d, off);
    }
    __shared__ float sh[8][2];
    int w = t >> 5;
    if ((t & 31) == 0) { sh[w][0] = s; sh[w][1] = d; }
    __syncthreads();
    if (t < H) {
        buf(esSel)[node * H + t] = sh[2 * t][0] + sh[2 * t + 1][0];
        buf(edSel)[node * H + t] = sh[2 * t][1] + sh[2 * t + 1][1];
    }
}

// ---------------- GAT1 scatter: ONE warp per edge, all 4 heads, no max pass ----------------
__global__ void gat_scatter4_k(const int* __restrict__ ei) {
    int e = (blockIdx.x * blockDim.x + threadIdx.x) >> 5;
    int lane = threadIdx.x & 31;
    if (e >= TE) return;
    int s, t;
    if (e < EE) { s = ei[e]; t = ei[EE + e]; } else { s = t = e - EE; }
    int h = lane >> 3;                        // 8 lanes per head
    float w = __expf(lrelu(g_es1[s * 4 + h] + g_ed1[t * 4 + h]));
    if ((lane & 7) == 0) atomicAdd(&g_den1[t * 4 + h], w);
    int d = lane * 8;                         // contiguous: covers all 256 floats
    const float4 v0 = *reinterpret_cast<const float4*>(&g_h1[s * 256 + d]);
    const float4 v1 = *reinterpret_cast<const float4*>(&g_h1[s * 256 + d + 4]);
    redAdd4(&g_agg1[t * 256 + d],     w * v0.x, w * v0.y, w * v0.z, w * v0.w);
    redAdd4(&g_agg1[t * 256 + d + 4], w * v1.x, w * v1.y, w * v1.z, w * v1.w);
}

// ---------------- GAT2 scatter (H=1): warp per 2 edges ----------------
__global__ void gat_scatter1_k(const int* __restrict__ ei) {
    int wt = (blockIdx.x * blockDim.x + threadIdx.x) >> 5;
    int lane = threadIdx.x & 31;
    int e = wt * 2 + (lane >> 4);
    if (e >= TE) return;
    int s, t;
    if (e < EE) { s = ei[e]; t = ei[EE + e]; } else { s = t = e - EE; }
    float w = __expf(lrelu(g_es2[s] + g_ed2[t]));
    if ((lane & 15) == 0) atomicAdd(&g_den2[t], w);
    int d = (lane & 15) << 2;
    const float4 hv = *reinterpret_cast<const float4*>(&g_h3[s * 64 + d]);
    redAdd4(&g_agg3[t * 64 + d], w * hv.x, w * hv.y, w * hv.z, w * hv.w);
}

__global__ void deg_k(const int* __restrict__ ei) {
    int i = blockIdx.x * blockDim.x + threadIdx.x;
    if (i >= TE) return;
    int t = (i < EE) ? ei[EE + i] : (i - EE);
    atomicAdd(&g_deg[t], 1.f);
}

// ---------------- GCN scatter: warp per 2 edges ----------------
__global__ void gcn_scatter_k(const int* __restrict__ ei) {
    int wt = (blockIdx.x * blockDim.x + threadIdx.x) >> 5;
    int lane = threadIdx.x & 31;
    int e = wt * 2 + (lane >> 4);
    if (e >= TE) return;
    int s, t;
    if (e < EE) { s = ei[e]; t = ei[EE + e]; } else { s = t = e - EE; }
    float nrm = rsqrtf(g_deg[s]) * rsqrtf(g_deg[t]);   // deg >= 1 (self loops)
    int d = (lane & 15) << 2;
    const float4 hv = *reinterpret_cast<const float4*>(&g_h2[s * 64 + d]);
    redAdd4(&g_agg2[t * 64 + d], nrm * hv.x, nrm * hv.y, nrm * hv.z, nrm * hv.w);
}

// ---------------- fused finalize + BN stats ----------------
// GAT1: agg1 = agg1/den1 + b1 (in place), accumulate sum/sumsq into s1.
__global__ void fin1_stats_k(const float* __restrict__ bias) {
    int f = threadIdx.x;           // 256 = F
    int h = f >> 6;
    float s = 0.f, sq = 0.f;
    for (int r = blockIdx.x; r < NN; r += gridDim.x) {
        float den = g_den1[r * 4 + h] + 1e-16f;
        float v = g_agg1[r * 256 + f] / den + bias[f];
        g_agg1[r * 256 + f] = v;
        s += v; sq += v * v;
    }
    atomicAdd(&g_s1[f], s);
    atomicAdd(&g_s1[256 + f], sq);
}

// GCN: agg2 += bg (in place), stats into s2. F=64, 4 rows per block-iter.
__global__ void gcnbias_stats_k(const float* __restrict__ bg) {
    int f = threadIdx.x & 63;
    int rr = threadIdx.x >> 6;
    float s = 0.f, sq = 0.f;
    for (int r = blockIdx.x * 4 + rr; r < NN; r += gridDim.x * 4) {
        float v = g_agg2[r * 64 + f] + bg[f];
        g_agg2[r * 64 + f] = v;
        s += v; sq += v * v;
    }
    atomicAdd(&g_s2[f], s);
    atomicAdd(&g_s2[64 + f], sq);
}

// GAT2: agg3 = agg3/den2 + b2 (in place), stats into s3.
__global__ void fin3_stats_k(const float* __restrict__ bias) {
    int f = threadIdx.x & 63;
    int rr = threadIdx.x >> 6;
    float s = 0.f, sq = 0.f;
    for (int r = blockIdx.x * 4 + rr; r < NN; r += gridDim.x * 4) {
        float den = g_den2[r] + 1e-16f;
        float v = g_agg3[r * 64 + f] / den + bias[f];
        g_agg3[r * 64 + f] = v;
        s += v; sq += v * v;
    }
    atomicAdd(&g_s3[f], s);
    atomicAdd(&g_s3[64 + f], sq);
}

// ---------------- BN prep: sc/sh from sums ----------------
__global__ void prep_k(int sSel, int scSel, int shSel,
                       const float* __restrict__ g, const float* __restrict__ beta, int F) {
    int f = blockIdx.x * blockDim.x + threadIdx.x;
    if (f >= F) return;
    const float* s = buf(sSel);
    const float invN = 1.f / (float)NN;
    float mu = s[f] * invN;
    float var = fmaxf(s[F + f] * invN - mu * mu, 0.f);
    float rs = rsqrtf(var + 1e-5f);
    buf(scSel)[f] = rs * g[f];
    buf(shSel)[f] = beta[f] - mu * rs * g[f];
}

// ---------------- host ----------------
static inline int cdiv(int a, int b) { return (a + b - 1) / b; }

extern "C" void kernel_launch(void* const* d_in, const int* in_sizes, int n_in,
                              void* d_out, int out_size) {
    const float* x   = (const float*)d_in[0];
    const int*   ei  = (const int*)  d_in[1];
    // d_in[2] = edge_attr (ignored by the model)
    const float* W1  = (const float*)d_in[3];
    const float* as1 = (const float*)d_in[4];
    const float* ad1 = (const float*)d_in[5];
    const float* b1  = (const float*)d_in[6];
    const float* g1  = (const float*)d_in[7];
    const float* be1 = (const float*)d_in[8];
    const float* Wg  = (const float*)d_in[9];
    const float* bg  = (const float*)d_in[10];
    const float* g2  = (const float*)d_in[11];
    const float* be2 = (const float*)d_in[12];
    const float* W2  = (const float*)d_in[13];
    const float* as2 = (const float*)d_in[14];
    const float* ad2 = (const float*)d_in[15];
    const float* b2  = (const float*)d_in[16];
    const float* g3  = (const float*)d_in[17];
    const float* be3 = (const float*)d_in[18];
    const float* Wp1 = (const float*)d_in[19];
    const float* bp1 = (const float*)d_in[20];
    const float* Wp2 = (const float*)d_in[21];
    const float* bp2 = (const float*)d_in[22];
    float* out = (float*)d_out;

    const int TPB = 256;

    // ---- zero scratch ----
    fill_k<<<cdiv(NN * 256, TPB), TPB>>>(B_AGG1, 0.f, NN * 256);
    fill_k<<<cdiv(NN * 64, TPB), TPB>>>(B_AGG2, 0.f, NN * 64);
    fill_k<<<cdiv(NN * 64, TPB), TPB>>>(B_AGG3, 0.f, NN * 64);
    fill_k<<<cdiv(NN * 4, TPB), TPB>>>(B_DEN1, 0.f, NN * 4);
    fill_k<<<cdiv(NN, TPB), TPB>>>(B_DEN2, 0.f, NN);
    fill_k<<<cdiv(NN, TPB), TPB>>>(B_DEG, 0.f, NN);
    fill_k<<<1, TPB>>>(B_S1, 0.f, 512);
    fill_k<<<1, TPB>>>(B_S2, 0.f, 128);
    fill_k<<<1, TPB>>>(B_S3, 0.f, 128);

    // degree (independent of features, run early)
    deg_k<<<cdiv(TE, TPB), TPB>>>(ei);

    // ---- GAT layer 1 ----
    {   // h1 = x @ W1   [N,128]x[128,256]
        dim3 grid(256 / 64, cdiv(NN, 128));
        gemm_k<<<grid, 256>>>(-1, x, W1, B_H1, nullptr, NN, 128, 256, -1, -1, 0, nullptr, 0);
    }
    attn_dots_k<<<NN, 256>>>(B_H1, as1, ad1, B_ES1, B_ED1, 4);
    gat_scatter4_k<<<cdiv(TE * 32, TPB), TPB>>>(ei);
    fin1_stats_k<<<512, 256>>>(b1);
    prep_k<<<1, 256>>>(B_S1, B_SC1, B_SH1, g1, be1, 256);

    // ---- GCN:  h2 = elu(bn(agg1)) @ Wg  (A-transform fused into GEMM) ----
    {
        dim3 grid(64 / 64, cdiv(NN, 128));
        gemm_k<<<grid, 256>>>(B_AGG1, nullptr, Wg, B_H2, nullptr, NN, 256, 64,
                              B_SC1, B_SH1, 1, nullptr, 0);
    }
    gcn_scatter_k<<<cdiv(cdiv(TE, 2) * 32, TPB), TPB>>>(ei);
    gcnbias_stats_k<<<512, 256>>>(bg);
    prep_k<<<1, 64>>>(B_S2, B_SC2, B_SH2, g2, be2, 64);

    // ---- GAT layer 2:  h3 = relu(bn(agg2)) @ W2 ----
    {
        dim3 grid(64 / 64, cdiv(NN, 128));
        gemm_k<<<grid, 256>>>(B_AGG2, nullptr, W2, B_H3, nullptr, NN, 64, 64,
                              B_SC2, B_SH2, 2, nullptr, 0);
    }
    attn_dots_k<<<NN, 64>>>(B_H3, as2, ad2, B_ES2, B_ED2, 1);
    gat_scatter1_k<<<cdiv(cdiv(TE, 2) * 32, TPB), TPB>>>(ei);
    fin3_stats_k<<<512, 256>>>(b2);
    prep_k<<<1, 64>>>(B_S3, B_SC3, B_SH3, g3, be3, 64);

    // ---- projector ----
    {   // p1 = relu( elu(bn(agg3)) @ Wp1 + bp1 )
        dim3 grid(128 / 64, cdiv(NN, 128));
        gemm_k<<<grid, 256>>>(B_AGG3, nullptr, Wp1, B_P1, nullptr, NN, 64, 128,
                              B_SC3, B_SH3, 1, bp1, 1);
    }
    {   // out = p1 @ Wp2 + bp2
        dim3 grid(64 / 64, cdiv(NN, 128));
        gemm_k<<<grid, 256>>>(B_P1, nullptr, Wp2, -1, out, NN, 128, 64,
                              -1, -1, 0, bp2, 0);
    }
}